// round 8
// baseline (speedup 1.0000x reference)
#include <cuda_runtime.h>
#include <cuda_fp16.h>
#include <math.h>

#define NN 50000
#define EE 800000
#define ETOT (EE + NN)
#define NEG_SLOPE 0.2f
#define EPS_DEN 1e-16f
#define FULLM 0xffffffffu

typedef unsigned long long ull;

// ---------------- scratch (static __device__, no allocs) ----------------
__device__ uint2 g_h1[NN * 32];       // layer1 features, fp16: 128 halves/node (4 per lane)
__device__ float g_asrc1[NN * 4];
__device__ float g_adst1[NN * 4];
__device__ float g_h2[NN * 2];
__device__ float g_asrc2[NN];
__device__ float g_adst2[NN];

__device__ int g_deg[NN];             // after k_offsets: includes self-loop
__device__ int g_rowstart[NN];
__device__ int g_cursor[NN];
__device__ int g_total;
__device__ int g_csrc[ETOT];          // CSR: src node per dst-grouped slot

// ---------------- packed f32x2 helpers (FFMA2 only reachable via PTX) ----------------
__device__ __forceinline__ void ffma2(ull& d, ull a, ull b) {
    asm("fma.rn.f32x2 %0, %1, %2, %3;" : "=l"(d) : "l"(a), "l"(b), "l"(d));
}
__device__ __forceinline__ ull pk2(float lo, float hi) {
    ull r; asm("mov.b64 %0, {%1, %2};" : "=l"(r) : "f"(lo), "f"(hi)); return r;
}
__device__ __forceinline__ float2 upk2(ull v) {
    float lo, hi; asm("mov.b64 {%0, %1}, %2;" : "=f"(lo), "=f"(hi) : "l"(v));
    return make_float2(lo, hi);
}

// ---------------- CSR build ----------------
// edge_index is int32 on device (JAX x64-disabled demotes int64->int32)
__global__ void k_count(const int* __restrict__ ei) {
    int t = blockIdx.x * blockDim.x + threadIdx.x;
    if (t >= EE / 8) return;
    int4 a = reinterpret_cast<const int4*>(ei + EE)[2 * t];
    int4 b = reinterpret_cast<const int4*>(ei + EE)[2 * t + 1];
    atomicAdd(&g_deg[a.x], 1); atomicAdd(&g_deg[a.y], 1);
    atomicAdd(&g_deg[a.z], 1); atomicAdd(&g_deg[a.w], 1);
    atomicAdd(&g_deg[b.x], 1); atomicAdd(&g_deg[b.y], 1);
    atomicAdd(&g_deg[b.z], 1); atomicAdd(&g_deg[b.w], 1);
}

// row offsets: intra-block scan + ONE global atomic per block (row order irrelevant);
// folds +1 self-loop into g_deg.
__global__ __launch_bounds__(256) void k_offsets() {
    __shared__ int wsum[8];
    __shared__ int sbase;
    int t = threadIdx.x;
    int n = blockIdx.x * 256 + t;
    int d = (n < NN) ? (g_deg[n] + 1) : 0;
    int lane = t & 31, wid = t >> 5;
    int incl = d;
#pragma unroll
    for (int off = 1; off < 32; off <<= 1) {
        int v = __shfl_up_sync(FULLM, incl, off);
        if (lane >= off) incl += v;
    }
    if (lane == 31) wsum[wid] = incl;
    __syncthreads();
    if (t == 0) {
        int run = 0;
#pragma unroll
        for (int w = 0; w < 8; w++) { int v = wsum[w]; wsum[w] = run; run += v; }
        sbase = atomicAdd(&g_total, run);
    }
    __syncthreads();
    if (n < NN) {
        int r = sbase + wsum[wid] + incl - d;
        g_deg[n] = d;
        g_rowstart[n] = r;
        g_cursor[n] = r;
    }
}

// scatter, 8 edges per thread (8 atomics in flight) + self-loop tail
__global__ void k_scatter(const int* __restrict__ ei) {
    int t = blockIdx.x * blockDim.x + threadIdx.x;
    if (t < EE / 8) {
        int4 sa = reinterpret_cast<const int4*>(ei)[2 * t];
        int4 sb = reinterpret_cast<const int4*>(ei)[2 * t + 1];
        int4 da = reinterpret_cast<const int4*>(ei + EE)[2 * t];
        int4 db = reinterpret_cast<const int4*>(ei + EE)[2 * t + 1];
        int p0 = atomicAdd(&g_cursor[da.x], 1);
        int p1 = atomicAdd(&g_cursor[da.y], 1);
        int p2 = atomicAdd(&g_cursor[da.z], 1);
        int p3 = atomicAdd(&g_cursor[da.w], 1);
        int p4 = atomicAdd(&g_cursor[db.x], 1);
        int p5 = atomicAdd(&g_cursor[db.y], 1);
        int p6 = atomicAdd(&g_cursor[db.z], 1);
        int p7 = atomicAdd(&g_cursor[db.w], 1);
        g_csrc[p0] = sa.x; g_csrc[p1] = sa.y; g_csrc[p2] = sa.z; g_csrc[p3] = sa.w;
        g_csrc[p4] = sb.x; g_csrc[p5] = sb.y; g_csrc[p6] = sb.z; g_csrc[p7] = sb.w;
    } else {
        int n = t - EE / 8;
        if (n < NN) {
            int pos = atomicAdd(&g_cursor[n], 1);
            g_csrc[pos] = n;
        }
    }
}

// ---------------- GEMM1: 4-way K-split cooperative tile ----------------
// 512 threads = 4 K-groups x 128 cols. Each thread caches 16 packed W pairs (32 regs).
// Per phase: 8 nodes staged in smem, partials to smem, combine + h1(fp16) + att dots.
#define GEMM_NPB 64
__global__ __launch_bounds__(512, 2) void k_gemm1(const float* __restrict__ x,
                                                  const float* __restrict__ W1,
                                                  const float* __restrict__ att_s,
                                                  const float* __restrict__ att_d) {
    __shared__ float sx[8 * 128];          // 8 x-rows
    __shared__ float spart[8 * 4 * 128];   // [node][group][col]
    const int tid = threadIdx.x;
    const int g = tid >> 7;                // K-group 0..3
    const int j = tid & 127;               // output column
    const int kbase = g << 5;              // 32 k-values per group

    ull wp[16];
#pragma unroll
    for (int m = 0; m < 16; m++)
        wp[m] = pk2(W1[(kbase + 2 * m) * 128 + j], W1[(kbase + 2 * m + 1) * 128 + j]);

    // combine-phase constants (thread covers cols c0,c1 of node tid>>6 each phase)
    const int c0 = (2 * tid) & 127, c1 = c0 + 1;
    const int nd = tid >> 6;
    const float as0 = att_s[c0], as1 = att_s[c1];
    const float ad0 = att_d[c0], ad1 = att_d[c1];

    const int blockbase = blockIdx.x * GEMM_NPB;
#pragma unroll 1
    for (int p = 0; p < 8; p++) {
        const int nb = blockbase + p * 8;
        if (nb >= NN) break;               // uniform across block
        if (tid < 256) {                   // stage 8 x-rows (float4)
            int row = tid >> 5, cc = tid & 31;
            int n = nb + row;
            if (n < NN)
                reinterpret_cast<float4*>(sx)[tid] =
                    reinterpret_cast<const float4*>(x)[n * 32 + cc];
        }
        __syncthreads();
#pragma unroll
        for (int nn = 0; nn < 8; nn++) {
            ull aA = 0ull, aB = 0ull;
            const float* xr = &sx[nn * 128 + kbase];
#pragma unroll
            for (int m = 0; m < 8; m++) {
                ulonglong2 v = *reinterpret_cast<const ulonglong2*>(xr + 4 * m);
                ffma2(aA, v.x, wp[2 * m]);
                ffma2(aB, v.y, wp[2 * m + 1]);
            }
            float2 fA = upk2(aA), fB = upk2(aB);
            spart[nn * 512 + g * 128 + j] = (fA.x + fA.y) + (fB.x + fB.y);
        }
        __syncthreads();
        {   // combine: thread -> (node nd, cols c0,c1); float2 loads conflict-free
            const float* pb = &spart[nd * 512];
            float2 t0 = *reinterpret_cast<const float2*>(pb + c0);
            float2 t1 = *reinterpret_cast<const float2*>(pb + 128 + c0);
            float2 t2 = *reinterpret_cast<const float2*>(pb + 256 + c0);
            float2 t3 = *reinterpret_cast<const float2*>(pb + 384 + c0);
            float s0 = (t0.x + t1.x) + (t2.x + t3.x);
            float s1 = (t0.y + t1.y) + (t2.y + t3.y);
            int n = nb + nd;
            if (n < NN)
                reinterpret_cast<__half2*>(g_h1)[n * 64 + (c0 >> 1)] =
                    __floats2half2_rn(s0, s1);
            float ps = s0 * as0 + s1 * as1;
            float pd = s0 * ad0 + s1 * ad1;
#pragma unroll
            for (int off = 8; off > 0; off >>= 1) {
                ps += __shfl_down_sync(FULLM, ps, off, 16);
                pd += __shfl_down_sync(FULLM, pd, off, 16);
            }
            if ((tid & 15) == 0 && n < NN) {
                int head = c0 >> 5;
                g_asrc1[n * 4 + head] = ps;
                g_adst1[n * 4 + head] = pd;
            }
        }
        __syncthreads();
    }
}

// ---------------- fused layer 1: softmax + aggregate + ELU + W2 proj ----------------
// one warp per destination node; fp16 h1 gathers (8B/lane/edge), unroll-8
__global__ __launch_bounds__(256) void k_layer1(const float* __restrict__ b1,
                                                const float* __restrict__ W2,
                                                const float* __restrict__ att_s2,
                                                const float* __restrict__ att_d2) {
    __shared__ int   ssrc[256];
    __shared__ float sex[256 * 4];
    int gt = blockIdx.x * blockDim.x + threadIdx.x;
    int n = gt >> 5;
    if (n >= NN) return;
    const int lane = gt & 31;
    const int head = lane >> 3;
    const int wslot = (threadIdx.x >> 5) * 32;

    const int beg = g_rowstart[n];
    const int end = beg + g_deg[n];
    const float4 adn = reinterpret_cast<const float4*>(g_adst1)[n];
    const uint2* __restrict__ h1v = g_h1;

    float acc0 = 0.0f, acc1 = 0.0f, acc2 = 0.0f, acc3 = 0.0f;
    float dx = 0.0f, dy = 0.0f, dz = 0.0f, dw = 0.0f;

    for (int c = beg; c < end; c += 32) {
        const int idx = c + lane;
        const int cnt = min(32, end - c);
        const int cnt8 = (cnt + 7) & ~7;
        __syncwarp(FULLM);
        {
            int s = g_csrc[min(idx, end - 1)];
            float4 as_ = reinterpret_cast<const float4*>(g_asrc1)[s];
            float v0 = as_.x + adn.x, v1 = as_.y + adn.y;
            float v2 = as_.z + adn.z, v3 = as_.w + adn.w;
            v0 = (v0 > 0.0f) ? v0 : NEG_SLOPE * v0;
            v1 = (v1 > 0.0f) ? v1 : NEG_SLOPE * v1;
            v2 = (v2 > 0.0f) ? v2 : NEG_SLOPE * v2;
            v3 = (v3 > 0.0f) ? v3 : NEG_SLOPE * v3;
            float e0 = expf(v0), e1 = expf(v1), e2 = expf(v2), e3 = expf(v3);
            if (idx >= end) { e0 = e1 = e2 = e3 = 0.0f; }
            dx += e0; dy += e1; dz += e2; dw += e3;
            ssrc[wslot + lane] = s;
            float* p = &sex[(wslot + lane) * 4];
            p[0] = e0; p[1] = e1; p[2] = e2; p[3] = e3;
        }
        __syncwarp(FULLM);
        for (int j = 0; j < cnt8; j += 8) {
            uint2 u[8];
#pragma unroll
            for (int i = 0; i < 8; i++) {
                int s = ssrc[wslot + j + i];
                u[i] = h1v[s * 32 + lane];
            }
#pragma unroll
            for (int i = 0; i < 8; i++) {
                float ex = sex[(wslot + j + i) * 4 + head];
                float2 a = __half22float2(*reinterpret_cast<__half2*>(&u[i].x));
                float2 b = __half22float2(*reinterpret_cast<__half2*>(&u[i].y));
                acc0 = fmaf(ex, a.x, acc0);
                acc1 = fmaf(ex, a.y, acc1);
                acc2 = fmaf(ex, b.x, acc2);
                acc3 = fmaf(ex, b.y, acc3);
            }
        }
    }
#pragma unroll
    for (int off = 16; off > 0; off >>= 1) {
        dx += __shfl_xor_sync(FULLM, dx, off);
        dy += __shfl_xor_sync(FULLM, dy, off);
        dz += __shfl_xor_sync(FULLM, dz, off);
        dw += __shfl_xor_sync(FULLM, dw, off);
    }
    float denh = (head == 0) ? dx : (head == 1) ? dy : (head == 2) ? dz : dw;
    float r = 1.0f / (denh + EPS_DEN);

    float av[4] = {acc0, acc1, acc2, acc3};
    float p0 = 0.0f, p1 = 0.0f;
#pragma unroll
    for (int m = 0; m < 4; m++) {
        int k = 4 * lane + m;
        float v = av[m] * r + b1[k];
        float ev = (v > 0.0f) ? v : expm1f(v);   // ELU
        p0 = fmaf(ev, W2[k * 2 + 0], p0);
        p1 = fmaf(ev, W2[k * 2 + 1], p1);
    }
#pragma unroll
    for (int off = 16; off > 0; off >>= 1) {
        p0 += __shfl_down_sync(FULLM, p0, off);
        p1 += __shfl_down_sync(FULLM, p1, off);
    }
    if (lane == 0) {
        g_h2[n * 2 + 0] = p0;
        g_h2[n * 2 + 1] = p1;
        g_asrc2[n] = p0 * att_s2[0] + p1 * att_s2[1];
        g_adst2[n] = p0 * att_d2[0] + p1 * att_d2[1];
    }
}

// ---------------- fused layer 2: softmax + aggregate + log_softmax ----------------
__global__ __launch_bounds__(256) void k_layer2(const float* __restrict__ b2,
                                                float* __restrict__ out) {
    int gt = blockIdx.x * blockDim.x + threadIdx.x;
    int n = gt >> 3;
    if (n >= NN) return;
    const int lane = gt & 7;

    const int beg = g_rowstart[n];
    const int end = beg + g_deg[n];
    const float adn = g_adst2[n];

    float den = 0.0f, o0 = 0.0f, o1 = 0.0f;
    for (int idx = beg + lane; idx < end; idx += 8) {
        int s = g_csrc[idx];
        float v = g_asrc2[s] + adn;
        v = (v > 0.0f) ? v : NEG_SLOPE * v;
        float ex = expf(v);
        float2 h = reinterpret_cast<const float2*>(g_h2)[s];
        den += ex;
        o0 = fmaf(ex, h.x, o0);
        o1 = fmaf(ex, h.y, o1);
    }
#pragma unroll
    for (int off = 4; off > 0; off >>= 1) {
        den += __shfl_down_sync(FULLM, den, off, 8);
        o0  += __shfl_down_sync(FULLM, o0, off, 8);
        o1  += __shfl_down_sync(FULLM, o1, off, 8);
    }
    if (lane == 0) {
        float r = 1.0f / (den + EPS_DEN);
        float a = o0 * r + b2[0];
        float b = o1 * r + b2[1];
        float m = fmaxf(a, b);
        float l = m + logf(expf(a - m) + expf(b - m));
        out[n * 2 + 0] = a - l;
        out[n * 2 + 1] = b - l;
    }
}

// ---------------- launch ----------------
extern "C" void kernel_launch(void* const* d_in, const int* in_sizes, int n_in,
                              void* d_out, int out_size) {
    const float* x    = (const float*)d_in[0];
    const int*   ei   = (const int*)d_in[1];
    const float* W1   = (const float*)d_in[2];
    const float* as1  = (const float*)d_in[3];
    const float* ad1  = (const float*)d_in[4];
    const float* b1   = (const float*)d_in[5];
    const float* W2   = (const float*)d_in[6];
    const float* as2  = (const float*)d_in[7];
    const float* ad2  = (const float*)d_in[8];
    const float* b2   = (const float*)d_in[9];
    float* out = (float*)d_out;

    (void)in_sizes; (void)n_in; (void)out_size;

    static cudaStream_t s_side = nullptr;
    static cudaEvent_t  s_evFork = nullptr, s_evJoin = nullptr;
    static void *p_deg = nullptr, *p_total = nullptr;
    if (s_side == nullptr) {
        cudaStreamCreateWithFlags(&s_side, cudaStreamNonBlocking);
        cudaEventCreateWithFlags(&s_evFork, cudaEventDisableTiming);
        cudaEventCreateWithFlags(&s_evJoin, cudaEventDisableTiming);
        cudaGetSymbolAddress(&p_deg, g_deg);
        cudaGetSymbolAddress(&p_total, g_total);
    }

    // fork: CSR build on side stream, gemm1 on main stream (disjoint state)
    cudaEventRecord(s_evFork, 0);
    cudaStreamWaitEvent(s_side, s_evFork, 0);

    cudaMemsetAsync(p_deg, 0, NN * sizeof(int), s_side);
    cudaMemsetAsync(p_total, 0, sizeof(int), s_side);
    k_count<<<(EE / 8 + 255) / 256, 256, 0, s_side>>>(ei);
    k_offsets<<<(NN + 255) / 256, 256, 0, s_side>>>();
    k_scatter<<<(EE / 8 + NN + 255) / 256, 256, 0, s_side>>>(ei);
    cudaEventRecord(s_evJoin, s_side);

    k_gemm1<<<(NN + GEMM_NPB - 1) / GEMM_NPB, 512>>>(x, W1, as1, ad1);

    // join: layer kernels need both CSR and gemm outputs
    cudaStreamWaitEvent(0, s_evJoin, 0);

    {
        long long tot = (long long)NN * 32;
        k_layer1<<<(int)((tot + 255) / 256), 256>>>(b1, W2, as2, ad2);
    }
    {
        long long tot = (long long)NN * 8;
        k_layer2<<<(int)((tot + 255) / 256), 256>>>(b2, out);
    }
}

// round 9
// speedup vs baseline: 1.7710x; 1.7710x over previous
#include <cuda_runtime.h>
#include <cuda_fp16.h>
#include <math.h>

#define NN 50000
#define EE 800000
#define ETOT (EE + NN)
#define NEG_SLOPE 0.2f
#define EPS_DEN 1e-16f
#define FULLM 0xffffffffu

typedef unsigned long long ull;

// ---------------- scratch (static __device__, no allocs) ----------------
__device__ uint2 g_h1[NN * 32];       // layer1 features, fp16: 128 halves/node (4 per lane)
__device__ float g_asrc1[NN * 4];
__device__ float g_adst1[NN * 4];
__device__ float g_h2[NN * 2];
__device__ float g_asrc2[NN];
__device__ float g_adst2[NN];

__device__ int g_deg[NN];             // after k_offsets: includes self-loop
__device__ int g_rowstart[NN];
__device__ int g_cursor[NN];
__device__ int g_total;
__device__ int g_csrc[ETOT];          // CSR: src node per dst-grouped slot

// ---------------- packed f32x2 helpers (FFMA2 only reachable via PTX) ----------------
__device__ __forceinline__ void ffma2(ull& d, ull a, ull b) {
    asm("fma.rn.f32x2 %0, %1, %2, %3;" : "=l"(d) : "l"(a), "l"(b), "l"(d));
}
__device__ __forceinline__ ull pk2(float lo, float hi) {
    ull r; asm("mov.b64 %0, {%1, %2};" : "=l"(r) : "f"(lo), "f"(hi)); return r;
}
__device__ __forceinline__ float2 upk2(ull v) {
    float lo, hi; asm("mov.b64 {%0, %1}, %2;" : "=f"(lo), "=f"(hi) : "l"(v));
    return make_float2(lo, hi);
}

// ---------------- CSR build ----------------
// edge_index is int32 on device (JAX x64-disabled demotes int64->int32)
__global__ void k_count(const int* __restrict__ ei) {
    int t = blockIdx.x * blockDim.x + threadIdx.x;
    if (t >= EE / 8) return;
    int4 a = reinterpret_cast<const int4*>(ei + EE)[2 * t];
    int4 b = reinterpret_cast<const int4*>(ei + EE)[2 * t + 1];
    atomicAdd(&g_deg[a.x], 1); atomicAdd(&g_deg[a.y], 1);
    atomicAdd(&g_deg[a.z], 1); atomicAdd(&g_deg[a.w], 1);
    atomicAdd(&g_deg[b.x], 1); atomicAdd(&g_deg[b.y], 1);
    atomicAdd(&g_deg[b.z], 1); atomicAdd(&g_deg[b.w], 1);
}

// row offsets: intra-block scan + ONE global atomic per block; folds +1 self-loop.
__global__ __launch_bounds__(256) void k_offsets() {
    __shared__ int wsum[8];
    __shared__ int sbase;
    int t = threadIdx.x;
    int n = blockIdx.x * 256 + t;
    int d = (n < NN) ? (g_deg[n] + 1) : 0;
    int lane = t & 31, wid = t >> 5;
    int incl = d;
#pragma unroll
    for (int off = 1; off < 32; off <<= 1) {
        int v = __shfl_up_sync(FULLM, incl, off);
        if (lane >= off) incl += v;
    }
    if (lane == 31) wsum[wid] = incl;
    __syncthreads();
    if (t == 0) {
        int run = 0;
#pragma unroll
        for (int w = 0; w < 8; w++) { int v = wsum[w]; wsum[w] = run; run += v; }
        sbase = atomicAdd(&g_total, run);
    }
    __syncthreads();
    if (n < NN) {
        int r = sbase + wsum[wid] + incl - d;
        g_deg[n] = d;
        g_rowstart[n] = r;
        g_cursor[n] = r;
    }
}

// scatter, 8 edges per thread + self-loop tail
__global__ void k_scatter(const int* __restrict__ ei) {
    int t = blockIdx.x * blockDim.x + threadIdx.x;
    if (t < EE / 8) {
        int4 sa = reinterpret_cast<const int4*>(ei)[2 * t];
        int4 sb = reinterpret_cast<const int4*>(ei)[2 * t + 1];
        int4 da = reinterpret_cast<const int4*>(ei + EE)[2 * t];
        int4 db = reinterpret_cast<const int4*>(ei + EE)[2 * t + 1];
        int p0 = atomicAdd(&g_cursor[da.x], 1);
        int p1 = atomicAdd(&g_cursor[da.y], 1);
        int p2 = atomicAdd(&g_cursor[da.z], 1);
        int p3 = atomicAdd(&g_cursor[da.w], 1);
        int p4 = atomicAdd(&g_cursor[db.x], 1);
        int p5 = atomicAdd(&g_cursor[db.y], 1);
        int p6 = atomicAdd(&g_cursor[db.z], 1);
        int p7 = atomicAdd(&g_cursor[db.w], 1);
        g_csrc[p0] = sa.x; g_csrc[p1] = sa.y; g_csrc[p2] = sa.z; g_csrc[p3] = sa.w;
        g_csrc[p4] = sb.x; g_csrc[p5] = sb.y; g_csrc[p6] = sb.z; g_csrc[p7] = sb.w;
    } else {
        int n = t - EE / 8;
        if (n < NN) {
            int pos = atomicAdd(&g_cursor[n], 1);
            g_csrc[pos] = n;
        }
    }
}

// ---------------- GEMM1: register-blocked tile ----------------
// 256 threads; block tile 64 nodes x 128 cols; thread tile 8 nodes x 4 cols.
// W (64KB) + x-tile (32KB) in dynamic smem; W staged once per block (grid-stride tiles).
#define NTILES ((NN + 63) / 64)
#define GEMM_BLOCKS 296
__global__ __launch_bounds__(256, 2) void k_gemm1(const float* __restrict__ x,
                                                  const float* __restrict__ W1,
                                                  const float* __restrict__ att_s,
                                                  const float* __restrict__ att_d) {
    extern __shared__ float smem[];
    float* sW = smem;                  // [128k][128col] = 64KB
    float* sX = smem + 128 * 128;      // [64n][128k]    = 32KB
    float4* sW4 = reinterpret_cast<float4*>(sW);
    float4* sX4 = reinterpret_cast<float4*>(sX);

    const int tid = threadIdx.x;
    const int cg = tid & 31;           // col group: cols 4cg..4cg+3 (lane id)
    const int ng = tid >> 5;           // node group: nodes 8ng..8ng+7 (warp id)

    // stage W once (coalesced float4 copy; W1 is [k][col] row-major already)
    for (int i = tid; i < 128 * 32; i += 256)
        sW4[i] = reinterpret_cast<const float4*>(W1)[i];

    const float as0 = att_s[4 * cg + 0], as1 = att_s[4 * cg + 1];
    const float as2 = att_s[4 * cg + 2], as3 = att_s[4 * cg + 3];
    const float ad0 = att_d[4 * cg + 0], ad1 = att_d[4 * cg + 1];
    const float ad2 = att_d[4 * cg + 2], ad3 = att_d[4 * cg + 3];

    for (int tile = blockIdx.x; tile < NTILES; tile += GEMM_BLOCKS) {
        const int n0 = tile * 64;
        __syncthreads();               // sW ready / sX safe to overwrite
        // stage x tile: 64 nodes x 32 float4, coalesced, zero-fill OOB
        for (int i = tid; i < 64 * 32; i += 256) {
            int n = n0 + (i >> 5);
            float4 v = make_float4(0.f, 0.f, 0.f, 0.f);
            if (n < NN) v = reinterpret_cast<const float4*>(x)[n * 32 + (i & 31)];
            sX4[i] = v;
        }
        __syncthreads();

        ull a01[8], a23[8];
#pragma unroll
        for (int nn = 0; nn < 8; nn++) { a01[nn] = 0ull; a23[nn] = 0ull; }

#pragma unroll 1
        for (int kq = 0; kq < 32; kq++) {
            // W for 4 k's, this thread's 4 cols (conflict-free LDS.128)
            float4 w0 = sW4[(4 * kq + 0) * 32 + cg];
            float4 w1 = sW4[(4 * kq + 1) * 32 + cg];
            float4 w2 = sW4[(4 * kq + 2) * 32 + cg];
            float4 w3 = sW4[(4 * kq + 3) * 32 + cg];
            ull w0a = pk2(w0.x, w0.y), w0b = pk2(w0.z, w0.w);
            ull w1a = pk2(w1.x, w1.y), w1b = pk2(w1.z, w1.w);
            ull w2a = pk2(w2.x, w2.y), w2b = pk2(w2.z, w2.w);
            ull w3a = pk2(w3.x, w3.y), w3b = pk2(w3.z, w3.w);
#pragma unroll
            for (int nn = 0; nn < 8; nn++) {
                float4 xv = sX4[(8 * ng + nn) * 32 + kq];   // broadcast (1 wavefront)
                ull x0 = pk2(xv.x, xv.x);
                ull x1 = pk2(xv.y, xv.y);
                ull x2 = pk2(xv.z, xv.z);
                ull x3 = pk2(xv.w, xv.w);
                ffma2(a01[nn], x0, w0a); ffma2(a23[nn], x0, w0b);
                ffma2(a01[nn], x1, w1a); ffma2(a23[nn], x1, w1b);
                ffma2(a01[nn], x2, w2a); ffma2(a23[nn], x2, w2b);
                ffma2(a01[nn], x3, w3a); ffma2(a23[nn], x3, w3b);
            }
        }

        // epilogue: h1 (fp16) + attention scalars
#pragma unroll
        for (int nn = 0; nn < 8; nn++) {
            int n = n0 + 8 * ng + nn;
            bool valid = (n < NN);
            float2 f01 = upk2(a01[nn]);
            float2 f23 = upk2(a23[nn]);
            if (valid) {
                __half2 ha = __floats2half2_rn(f01.x, f01.y);
                __half2 hb = __floats2half2_rn(f23.x, f23.y);
                uint2 u;
                u.x = *reinterpret_cast<unsigned*>(&ha);
                u.y = *reinterpret_cast<unsigned*>(&hb);
                g_h1[n * 32 + cg] = u;
            }
            float ps = f01.x * as0 + f01.y * as1 + f23.x * as2 + f23.y * as3;
            float pd = f01.x * ad0 + f01.y * ad1 + f23.x * ad2 + f23.y * ad3;
#pragma unroll
            for (int off = 4; off > 0; off >>= 1) {
                ps += __shfl_down_sync(FULLM, ps, off, 8);
                pd += __shfl_down_sync(FULLM, pd, off, 8);
            }
            if ((cg & 7) == 0 && valid) {
                g_asrc1[n * 4 + (cg >> 3)] = ps;
                g_adst1[n * 4 + (cg >> 3)] = pd;
            }
        }
    }
}

// ---------------- fused layer 1: softmax + aggregate + ELU + W2 proj ----------------
// one warp per destination node; fp16 h1 gathers (8B/lane/edge), unroll-8
__global__ __launch_bounds__(256) void k_layer1(const float* __restrict__ b1,
                                                const float* __restrict__ W2,
                                                const float* __restrict__ att_s2,
                                                const float* __restrict__ att_d2) {
    __shared__ int   ssrc[256];
    __shared__ float sex[256 * 4];
    int gt = blockIdx.x * blockDim.x + threadIdx.x;
    int n = gt >> 5;
    if (n >= NN) return;
    const int lane = gt & 31;
    const int head = lane >> 3;
    const int wslot = (threadIdx.x >> 5) * 32;

    const int beg = g_rowstart[n];
    const int end = beg + g_deg[n];
    const float4 adn = reinterpret_cast<const float4*>(g_adst1)[n];
    const uint2* __restrict__ h1v = g_h1;

    float acc0 = 0.0f, acc1 = 0.0f, acc2 = 0.0f, acc3 = 0.0f;
    float dx = 0.0f, dy = 0.0f, dz = 0.0f, dw = 0.0f;

    for (int c = beg; c < end; c += 32) {
        const int idx = c + lane;
        const int cnt = min(32, end - c);
        const int cnt8 = (cnt + 7) & ~7;
        __syncwarp(FULLM);
        {
            int s = g_csrc[min(idx, end - 1)];
            float4 as_ = reinterpret_cast<const float4*>(g_asrc1)[s];
            float v0 = as_.x + adn.x, v1 = as_.y + adn.y;
            float v2 = as_.z + adn.z, v3 = as_.w + adn.w;
            v0 = (v0 > 0.0f) ? v0 : NEG_SLOPE * v0;
            v1 = (v1 > 0.0f) ? v1 : NEG_SLOPE * v1;
            v2 = (v2 > 0.0f) ? v2 : NEG_SLOPE * v2;
            v3 = (v3 > 0.0f) ? v3 : NEG_SLOPE * v3;
            float e0 = expf(v0), e1 = expf(v1), e2 = expf(v2), e3 = expf(v3);
            if (idx >= end) { e0 = e1 = e2 = e3 = 0.0f; }
            dx += e0; dy += e1; dz += e2; dw += e3;
            ssrc[wslot + lane] = s;
            float* p = &sex[(wslot + lane) * 4];
            p[0] = e0; p[1] = e1; p[2] = e2; p[3] = e3;
        }
        __syncwarp(FULLM);
        for (int j = 0; j < cnt8; j += 8) {
            uint2 u[8];
#pragma unroll
            for (int i = 0; i < 8; i++) {
                int s = ssrc[wslot + j + i];
                u[i] = h1v[s * 32 + lane];
            }
#pragma unroll
            for (int i = 0; i < 8; i++) {
                float ex = sex[(wslot + j + i) * 4 + head];
                float2 a = __half22float2(*reinterpret_cast<__half2*>(&u[i].x));
                float2 b = __half22float2(*reinterpret_cast<__half2*>(&u[i].y));
                acc0 = fmaf(ex, a.x, acc0);
                acc1 = fmaf(ex, a.y, acc1);
                acc2 = fmaf(ex, b.x, acc2);
                acc3 = fmaf(ex, b.y, acc3);
            }
        }
    }
#pragma unroll
    for (int off = 16; off > 0; off >>= 1) {
        dx += __shfl_xor_sync(FULLM, dx, off);
        dy += __shfl_xor_sync(FULLM, dy, off);
        dz += __shfl_xor_sync(FULLM, dz, off);
        dw += __shfl_xor_sync(FULLM, dw, off);
    }
    float denh = (head == 0) ? dx : (head == 1) ? dy : (head == 2) ? dz : dw;
    float r = 1.0f / (denh + EPS_DEN);

    float av[4] = {acc0, acc1, acc2, acc3};
    float p0 = 0.0f, p1 = 0.0f;
#pragma unroll
    for (int m = 0; m < 4; m++) {
        int k = 4 * lane + m;
        float v = av[m] * r + b1[k];
        float ev = (v > 0.0f) ? v : expm1f(v);   // ELU
        p0 = fmaf(ev, W2[k * 2 + 0], p0);
        p1 = fmaf(ev, W2[k * 2 + 1], p1);
    }
#pragma unroll
    for (int off = 16; off > 0; off >>= 1) {
        p0 += __shfl_down_sync(FULLM, p0, off);
        p1 += __shfl_down_sync(FULLM, p1, off);
    }
    if (lane == 0) {
        g_h2[n * 2 + 0] = p0;
        g_h2[n * 2 + 1] = p1;
        g_asrc2[n] = p0 * att_s2[0] + p1 * att_s2[1];
        g_adst2[n] = p0 * att_d2[0] + p1 * att_d2[1];
    }
}

// ---------------- fused layer 2: softmax + aggregate + log_softmax ----------------
__global__ __launch_bounds__(256) void k_layer2(const float* __restrict__ b2,
                                                float* __restrict__ out) {
    int gt = blockIdx.x * blockDim.x + threadIdx.x;
    int n = gt >> 3;
    if (n >= NN) return;
    const int lane = gt & 7;

    const int beg = g_rowstart[n];
    const int end = beg + g_deg[n];
    const float adn = g_adst2[n];

    float den = 0.0f, o0 = 0.0f, o1 = 0.0f;
    for (int idx = beg + lane; idx < end; idx += 8) {
        int s = g_csrc[idx];
        float v = g_asrc2[s] + adn;
        v = (v > 0.0f) ? v : NEG_SLOPE * v;
        float ex = expf(v);
        float2 h = reinterpret_cast<const float2*>(g_h2)[s];
        den += ex;
        o0 = fmaf(ex, h.x, o0);
        o1 = fmaf(ex, h.y, o1);
    }
#pragma unroll
    for (int off = 4; off > 0; off >>= 1) {
        den += __shfl_down_sync(FULLM, den, off, 8);
        o0  += __shfl_down_sync(FULLM, o0, off, 8);
        o1  += __shfl_down_sync(FULLM, o1, off, 8);
    }
    if (lane == 0) {
        float r = 1.0f / (den + EPS_DEN);
        float a = o0 * r + b2[0];
        float b = o1 * r + b2[1];
        float m = fmaxf(a, b);
        float l = m + logf(expf(a - m) + expf(b - m));
        out[n * 2 + 0] = a - l;
        out[n * 2 + 1] = b - l;
    }
}

// ---------------- launch ----------------
extern "C" void kernel_launch(void* const* d_in, const int* in_sizes, int n_in,
                              void* d_out, int out_size) {
    const float* x    = (const float*)d_in[0];
    const int*   ei   = (const int*)d_in[1];
    const float* W1   = (const float*)d_in[2];
    const float* as1  = (const float*)d_in[3];
    const float* ad1  = (const float*)d_in[4];
    const float* b1   = (const float*)d_in[5];
    const float* W2   = (const float*)d_in[6];
    const float* as2  = (const float*)d_in[7];
    const float* ad2  = (const float*)d_in[8];
    const float* b2   = (const float*)d_in[9];
    float* out = (float*)d_out;

    (void)in_sizes; (void)n_in; (void)out_size;

    static cudaStream_t s_side = nullptr;
    static cudaEvent_t  s_evFork = nullptr, s_evJoin = nullptr;
    static void *p_deg = nullptr, *p_total = nullptr;
    const int GEMM_SMEM = (128 * 128 + 64 * 128) * sizeof(float);   // 96 KB
    if (s_side == nullptr) {
        cudaStreamCreateWithFlags(&s_side, cudaStreamNonBlocking);
        cudaEventCreateWithFlags(&s_evFork, cudaEventDisableTiming);
        cudaEventCreateWithFlags(&s_evJoin, cudaEventDisableTiming);
        cudaGetSymbolAddress(&p_deg, g_deg);
        cudaGetSymbolAddress(&p_total, g_total);
        cudaFuncSetAttribute(k_gemm1, cudaFuncAttributeMaxDynamicSharedMemorySize, GEMM_SMEM);
    }

    // fork: CSR build on side stream, gemm1 on main stream (disjoint state)
    cudaEventRecord(s_evFork, 0);
    cudaStreamWaitEvent(s_side, s_evFork, 0);

    cudaMemsetAsync(p_deg, 0, NN * sizeof(int), s_side);
    cudaMemsetAsync(p_total, 0, sizeof(int), s_side);
    k_count<<<(EE / 8 + 255) / 256, 256, 0, s_side>>>(ei);
    k_offsets<<<(NN + 255) / 256, 256, 0, s_side>>>();
    k_scatter<<<(EE / 8 + NN + 255) / 256, 256, 0, s_side>>>(ei);
    cudaEventRecord(s_evJoin, s_side);

    k_gemm1<<<GEMM_BLOCKS, 256, GEMM_SMEM>>>(x, W1, as1, ad1);

    // join: layer kernels need both CSR and gemm outputs
    cudaStreamWaitEvent(0, s_evJoin, 0);

    {
        long long tot = (long long)NN * 32;
        k_layer1<<<(int)((tot + 255) / 256), 256>>>(b1, W2, as2, ad2);
    }
    {
        long long tot = (long long)NN * 8;
        k_layer2<<<(int)((tot + 255) / 256), 256>>>(b2, out);
    }
}